// round 1
// baseline (speedup 1.0000x reference)
#include <cuda_runtime.h>

#define N_NODES  100000
#define N_EDGES  1600000
#define HIDDEN   64
#define N_GRAPHS 64

// ---------------- scratch (no allocations allowed) ----------------
__device__ float g_deg [N_NODES];     // deg, >= 1 (self loop)
__device__ float g_dinv[N_NODES];     // rsqrt(deg)
__device__ float g_p   [N_NODES];     // scalar layer-1 aggregation
__device__ float g_y   [2 * N_NODES]; // per-node 2-vector after W2
__device__ float g_acc [2 * N_NODES]; // layer-2 conv accumulator
__device__ float g_stats[2];          // sum(p), sum(p^2)
__device__ float g_gsum[2 * N_GRAPHS];
__device__ float g_gcnt[N_GRAPHS];
__device__ unsigned g_done;

// ---------------- K0: init ----------------
__global__ void k_init() {
    int i = blockIdx.x * blockDim.x + threadIdx.x;
    if (i < N_NODES) g_deg[i] = 1.0f;               // self-loop weight
    if (i < 2 * N_GRAPHS) g_gsum[i] = 0.0f;
    if (i < N_GRAPHS)     g_gcnt[i] = 0.0f;
    if (i < 2)            g_stats[i] = 0.0f;
    if (i == 0)           g_done = 0u;
}

// ---------------- K1: deg[dst] += ew ----------------
__global__ void k_deg(const int* __restrict__ dst, const float* __restrict__ ew) {
    int e = blockIdx.x * blockDim.x + threadIdx.x;
    if (e >= N_EDGES / 4) return;
    int4   d4 = reinterpret_cast<const int4*>(dst)[e];
    float4 w4 = reinterpret_cast<const float4*>(ew)[e];
    atomicAdd(&g_deg[d4.x], w4.x);
    atomicAdd(&g_deg[d4.y], w4.y);
    atomicAdd(&g_deg[d4.z], w4.z);
    atomicAdd(&g_deg[d4.w], w4.w);
}

// ---------------- K2: dinv = rsqrt(deg); p = x/deg (self-loop term) ----------------
__global__ void k_dinv(const float* __restrict__ x) {
    int n = blockIdx.x * blockDim.x + threadIdx.x;
    if (n >= N_NODES) return;
    float d  = g_deg[n];
    float di = rsqrtf(d);
    g_dinv[n] = di;
    g_p[n]    = x[n] * di * di;
}

// ---------------- K3: p[dst] += dinv[s]*ew*dinv[d]*x[s] ----------------
__global__ void k_edge1(const int* __restrict__ src, const int* __restrict__ dst,
                        const float* __restrict__ ew, const float* __restrict__ x) {
    int e = blockIdx.x * blockDim.x + threadIdx.x;
    if (e >= N_EDGES / 4) return;
    int4   s4 = reinterpret_cast<const int4*>(src)[e];
    int4   d4 = reinterpret_cast<const int4*>(dst)[e];
    float4 w4 = reinterpret_cast<const float4*>(ew)[e];
    float c0 = g_dinv[s4.x] * w4.x * g_dinv[d4.x] * x[s4.x];
    float c1 = g_dinv[s4.y] * w4.y * g_dinv[d4.y] * x[s4.y];
    float c2 = g_dinv[s4.z] * w4.z * g_dinv[d4.z] * x[s4.z];
    float c3 = g_dinv[s4.w] * w4.w * g_dinv[d4.w] * x[s4.w];
    atomicAdd(&g_p[d4.x], c0);
    atomicAdd(&g_p[d4.y], c1);
    atomicAdd(&g_p[d4.z], c2);
    atomicAdd(&g_p[d4.w], c3);
}

// ---------------- K4: sum(p), sum(p^2) ----------------
__global__ void k_stats() {
    float s1 = 0.f, s2 = 0.f;
    for (int n = blockIdx.x * blockDim.x + threadIdx.x; n < N_NODES;
         n += gridDim.x * blockDim.x) {
        float v = g_p[n];
        s1 += v;
        s2 += v * v;
    }
    #pragma unroll
    for (int o = 16; o; o >>= 1) {
        s1 += __shfl_down_sync(0xFFFFFFFFu, s1, o);
        s2 += __shfl_down_sync(0xFFFFFFFFu, s2, o);
    }
    __shared__ float sh1[8], sh2[8];
    int wid = threadIdx.x >> 5, lid = threadIdx.x & 31;
    if (lid == 0) { sh1[wid] = s1; sh2[wid] = s2; }
    __syncthreads();
    if (wid == 0) {
        s1 = (lid < 8) ? sh1[lid] : 0.f;
        s2 = (lid < 8) ? sh2[lid] : 0.f;
        #pragma unroll
        for (int o = 4; o; o >>= 1) {
            s1 += __shfl_down_sync(0xFFFFFFFFu, s1, o);
            s2 += __shfl_down_sync(0xFFFFFFFFu, s2, o);
        }
        if (lid == 0) {
            atomicAdd(&g_stats[0], s1);
            atomicAdd(&g_stats[1], s2);
        }
    }
}

// ---------------- K5: per-node BN+ReLU+W2, and self-loop init for conv2 ----------------
__global__ void k_node(const float* __restrict__ W1, const float* __restrict__ gamma,
                       const float* __restrict__ beta, const float* __restrict__ W2,
                       const float* __restrict__ b2) {
    __shared__ float s_a[HIDDEN], s_b[HIDDEN], s_w0[HIDDEN], s_w1[HIDDEN];
    float mp  = g_stats[0] * (1.0f / N_NODES);
    float var = g_stats[1] * (1.0f / N_NODES) - mp * mp;
    int t = threadIdx.x;
    if (t < HIDDEN) {
        float w1c = W1[t];
        s_a[t]  = w1c * rsqrtf(var * w1c * w1c + 1e-5f) * gamma[t];
        s_b[t]  = beta[t];
        s_w0[t] = W2[2 * t];
        s_w1[t] = W2[2 * t + 1];
    }
    __syncthreads();
    int n = blockIdx.x * blockDim.x + threadIdx.x;
    if (n >= N_NODES) return;
    float pm = g_p[n] - mp;
    float y0 = 0.f, y1 = 0.f;
    #pragma unroll 16
    for (int c = 0; c < HIDDEN; c++) {
        float h = fmaf(pm, s_a[c], s_b[c]);
        h = fmaxf(h, 0.f);
        y0 = fmaf(h, s_w0[c], y0);
        y1 = fmaf(h, s_w1[c], y1);
    }
    g_y[2 * n]     = y0;
    g_y[2 * n + 1] = y1;
    float di = g_dinv[n];
    float sl = di * di;                 // self-loop norm = 1/deg
    g_acc[2 * n]     = fmaf(y0, sl, b2[0]);
    g_acc[2 * n + 1] = fmaf(y1, sl, b2[1]);
}

// ---------------- K6: acc[dst] += norm * y[src] ----------------
__global__ void k_edge2(const int* __restrict__ src, const int* __restrict__ dst,
                        const float* __restrict__ ew) {
    int e = blockIdx.x * blockDim.x + threadIdx.x;
    if (e >= N_EDGES / 4) return;
    int4   s4 = reinterpret_cast<const int4*>(src)[e];
    int4   d4 = reinterpret_cast<const int4*>(dst)[e];
    float4 w4 = reinterpret_cast<const float4*>(ew)[e];

    float c0 = g_dinv[s4.x] * w4.x * g_dinv[d4.x];
    float c1 = g_dinv[s4.y] * w4.y * g_dinv[d4.y];
    float c2 = g_dinv[s4.z] * w4.z * g_dinv[d4.z];
    float c3 = g_dinv[s4.w] * w4.w * g_dinv[d4.w];
    float2 y0 = *reinterpret_cast<const float2*>(&g_y[2 * s4.x]);
    float2 y1 = *reinterpret_cast<const float2*>(&g_y[2 * s4.y]);
    float2 y2 = *reinterpret_cast<const float2*>(&g_y[2 * s4.z]);
    float2 y3 = *reinterpret_cast<const float2*>(&g_y[2 * s4.w]);
    atomicAdd(&g_acc[2 * d4.x],     c0 * y0.x);
    atomicAdd(&g_acc[2 * d4.x + 1], c0 * y0.y);
    atomicAdd(&g_acc[2 * d4.y],     c1 * y1.x);
    atomicAdd(&g_acc[2 * d4.y + 1], c1 * y1.y);
    atomicAdd(&g_acc[2 * d4.z],     c2 * y2.x);
    atomicAdd(&g_acc[2 * d4.z + 1], c2 * y2.y);
    atomicAdd(&g_acc[2 * d4.w],     c3 * y3.x);
    atomicAdd(&g_acc[2 * d4.w + 1], c3 * y3.y);
}

// ---------------- K7: pooling (shared-mem reduce, last block finalizes) ----------------
__global__ void k_pool(const int* __restrict__ batch, float* __restrict__ out,
                       int nblocks) {
    __shared__ float ssum[2 * N_GRAPHS];
    __shared__ float scnt[N_GRAPHS];
    __shared__ bool  isLast;
    int t = threadIdx.x;
    if (t < 2 * N_GRAPHS) ssum[t] = 0.f;
    if (t < N_GRAPHS)     scnt[t] = 0.f;
    __syncthreads();

    int n = blockIdx.x * blockDim.x + t;
    if (n < N_NODES) {
        int g = batch[n];
        atomicAdd(&ssum[2 * g],     g_acc[2 * n]);
        atomicAdd(&ssum[2 * g + 1], g_acc[2 * n + 1]);
        atomicAdd(&scnt[g], 1.0f);
    }
    __syncthreads();
    if (t < 2 * N_GRAPHS && ssum[t] != 0.f) atomicAdd(&g_gsum[t], ssum[t]);
    if (t < N_GRAPHS     && scnt[t] != 0.f) atomicAdd(&g_gcnt[t], scnt[t]);

    // last-block finalize
    __threadfence();
    __syncthreads();
    if (t == 0) isLast = (atomicAdd(&g_done, 1u) == (unsigned)(nblocks - 1));
    __syncthreads();
    if (isLast && t < 2 * N_GRAPHS) {
        float cnt = fmaxf(g_gcnt[t >> 1], 1.0f);
        out[t] = g_gsum[t] / cnt;
    }
}

// ---------------- launch ----------------
extern "C" void kernel_launch(void* const* d_in, const int* in_sizes, int n_in,
                              void* d_out, int out_size) {
    const float* x     = (const float*)d_in[0];
    const int*   ei    = (const int*)  d_in[1];
    const float* ew    = (const float*)d_in[2];
    const int*   batch = (const int*)  d_in[3];
    const float* W1    = (const float*)d_in[4];
    const float* gamma = (const float*)d_in[6];
    const float* beta  = (const float*)d_in[7];
    const float* W2    = (const float*)d_in[8];
    const float* b2    = (const float*)d_in[9];
    const int* src = ei;
    const int* dst = ei + N_EDGES;
    float* out = (float*)d_out;

    const int NT = 256;
    const int nodeBlocks = (N_NODES + NT - 1) / NT;            // 391
    const int edgeBlocks = (N_EDGES / 4 + NT - 1) / NT;        // 1563

    k_init <<<nodeBlocks, NT>>>();
    k_deg  <<<edgeBlocks, NT>>>(dst, ew);
    k_dinv <<<nodeBlocks, NT>>>(x);
    k_edge1<<<edgeBlocks, NT>>>(src, dst, ew, x);
    k_stats<<<nodeBlocks, NT>>>();
    k_node <<<nodeBlocks, NT>>>(W1, gamma, beta, W2, b2);
    k_edge2<<<edgeBlocks, NT>>>(src, dst, ew);
    k_pool <<<nodeBlocks, NT>>>(batch, out, nodeBlocks);
}

// round 2
// speedup vs baseline: 1.1562x; 1.1562x over previous
#include <cuda_runtime.h>

#define N_NODES  100000
#define N_EDGES  1600000
#define HIDDEN   64
#define N_GRAPHS 64

// ---------------- scratch ----------------
__device__ float g_deg  [N_NODES];     // edge-weight degree (excl. self loop)
__device__ float g_dinv [N_NODES];     // rsqrt(deg+1)
__device__ float g_q    [N_NODES];     // dinv*x   (gather source, layer 1)
__device__ float g_praw [N_NODES];     // un-normalized layer-1 aggregation
__device__ float g_ysc  [2 * N_NODES]; // dinv*y   (gather source, layer 2)
__device__ float g_araw [2 * N_NODES]; // un-normalized layer-2 aggregation
__device__ float g_stats[2];           // sum(p), sum(p^2)
__device__ float g_gsum [2 * N_GRAPHS];
__device__ float g_gcnt [N_GRAPHS];
__device__ unsigned g_done;

// ---------------- K0: zero accumulators ----------------
__global__ void k_init() {
    int i = blockIdx.x * blockDim.x + threadIdx.x;
    if (i < N_NODES) g_deg[i] = 0.0f;
    if (i < 2 * N_GRAPHS) g_gsum[i] = 0.0f;
    if (i < N_GRAPHS)     g_gcnt[i] = 0.0f;
    if (i < 2)            g_stats[i] = 0.0f;
    if (i == 0)           g_done = 0u;
}

// ---------------- K1: deg[dst] += ew ----------------
__global__ void k_deg(const int* __restrict__ dst, const float* __restrict__ ew) {
    int e = blockIdx.x * blockDim.x + threadIdx.x;
    if (e >= N_EDGES / 4) return;
    int4   d4 = reinterpret_cast<const int4*>(dst)[e];
    float4 w4 = reinterpret_cast<const float4*>(ew)[e];
    atomicAdd(&g_deg[d4.x], w4.x);
    atomicAdd(&g_deg[d4.y], w4.y);
    atomicAdd(&g_deg[d4.z], w4.z);
    atomicAdd(&g_deg[d4.w], w4.w);
}

// ---------------- K2: dinv, q = dinv*x, praw init = q ----------------
__global__ void k_dinv(const float* __restrict__ x) {
    int n = blockIdx.x * blockDim.x + threadIdx.x;
    if (n >= N_NODES) return;
    float d  = g_deg[n] + 1.0f;          // + self loop
    float di = rsqrtf(d);
    float q  = x[n] * di;
    g_dinv[n] = di;
    g_q[n]    = q;
    g_praw[n] = q;                        // self-loop contribution (pre-dinv[d])
}

// ---------------- K3: praw[dst] += w * q[src]  (ONE random gather) ----------------
__global__ void k_edge1(const int* __restrict__ src, const int* __restrict__ dst,
                        const float* __restrict__ ew) {
    int e = blockIdx.x * blockDim.x + threadIdx.x;
    if (e >= N_EDGES / 4) return;
    int4   s4 = reinterpret_cast<const int4*>(src)[e];
    int4   d4 = reinterpret_cast<const int4*>(dst)[e];
    float4 w4 = reinterpret_cast<const float4*>(ew)[e];
    float m0 = w4.x * __ldg(&g_q[s4.x]);
    float m1 = w4.y * __ldg(&g_q[s4.y]);
    float m2 = w4.z * __ldg(&g_q[s4.z]);
    float m3 = w4.w * __ldg(&g_q[s4.w]);
    atomicAdd(&g_praw[d4.x], m0);
    atomicAdd(&g_praw[d4.y], m1);
    atomicAdd(&g_praw[d4.z], m2);
    atomicAdd(&g_praw[d4.w], m3);
}

// ---------------- K4: stats over p = dinv*praw ----------------
__global__ void k_stats() {
    float s1 = 0.f, s2 = 0.f;
    for (int n = blockIdx.x * blockDim.x + threadIdx.x; n < N_NODES;
         n += gridDim.x * blockDim.x) {
        float v = g_dinv[n] * g_praw[n];
        s1 += v;
        s2 += v * v;
    }
    #pragma unroll
    for (int o = 16; o; o >>= 1) {
        s1 += __shfl_down_sync(0xFFFFFFFFu, s1, o);
        s2 += __shfl_down_sync(0xFFFFFFFFu, s2, o);
    }
    __shared__ float sh1[8], sh2[8];
    int wid = threadIdx.x >> 5, lid = threadIdx.x & 31;
    if (lid == 0) { sh1[wid] = s1; sh2[wid] = s2; }
    __syncthreads();
    if (wid == 0) {
        s1 = (lid < 8) ? sh1[lid] : 0.f;
        s2 = (lid < 8) ? sh2[lid] : 0.f;
        #pragma unroll
        for (int o = 4; o; o >>= 1) {
            s1 += __shfl_down_sync(0xFFFFFFFFu, s1, o);
            s2 += __shfl_down_sync(0xFFFFFFFFu, s2, o);
        }
        if (lid == 0) {
            atomicAdd(&g_stats[0], s1);
            atomicAdd(&g_stats[1], s2);
        }
    }
}

// ---------------- K5: BN+ReLU+W2; ysc = dinv*y; araw init = ysc ----------------
__global__ void k_node(const float* __restrict__ W1, const float* __restrict__ gamma,
                       const float* __restrict__ beta, const float* __restrict__ W2) {
    __shared__ float s_a[HIDDEN], s_b[HIDDEN], s_w0[HIDDEN], s_w1[HIDDEN];
    float mp  = g_stats[0] * (1.0f / N_NODES);
    float var = g_stats[1] * (1.0f / N_NODES) - mp * mp;
    int t = threadIdx.x;
    if (t < HIDDEN) {
        float w1c = W1[t];
        s_a[t]  = w1c * rsqrtf(var * w1c * w1c + 1e-5f) * gamma[t];
        s_b[t]  = beta[t];
        s_w0[t] = W2[2 * t];
        s_w1[t] = W2[2 * t + 1];
    }
    __syncthreads();
    int n = blockIdx.x * blockDim.x + threadIdx.x;
    if (n >= N_NODES) return;
    float di = g_dinv[n];
    float pm = di * g_praw[n] - mp;
    float y0 = 0.f, y1 = 0.f;
    #pragma unroll 16
    for (int c = 0; c < HIDDEN; c++) {
        float h = fmaf(pm, s_a[c], s_b[c]);
        h = fmaxf(h, 0.f);
        y0 = fmaf(h, s_w0[c], y0);
        y1 = fmaf(h, s_w1[c], y1);
    }
    float2 ysc = make_float2(y0 * di, y1 * di);
    *reinterpret_cast<float2*>(&g_ysc[2 * n])  = ysc;  // gather source
    *reinterpret_cast<float2*>(&g_araw[2 * n]) = ysc;  // self-loop init
}

// ---------------- K6: araw[dst] += w * ysc[src]  (ONE float2 gather) ----------------
__global__ void k_edge2(const int* __restrict__ src, const int* __restrict__ dst,
                        const float* __restrict__ ew) {
    int e = blockIdx.x * blockDim.x + threadIdx.x;
    if (e >= N_EDGES / 4) return;
    int4   s4 = reinterpret_cast<const int4*>(src)[e];
    int4   d4 = reinterpret_cast<const int4*>(dst)[e];
    float4 w4 = reinterpret_cast<const float4*>(ew)[e];
    float2 y0 = *reinterpret_cast<const float2*>(&g_ysc[2 * s4.x]);
    float2 y1 = *reinterpret_cast<const float2*>(&g_ysc[2 * s4.y]);
    float2 y2 = *reinterpret_cast<const float2*>(&g_ysc[2 * s4.z]);
    float2 y3 = *reinterpret_cast<const float2*>(&g_ysc[2 * s4.w]);
    atomicAdd(&g_araw[2 * d4.x],     w4.x * y0.x);
    atomicAdd(&g_araw[2 * d4.x + 1], w4.x * y0.y);
    atomicAdd(&g_araw[2 * d4.y],     w4.y * y1.x);
    atomicAdd(&g_araw[2 * d4.y + 1], w4.y * y1.y);
    atomicAdd(&g_araw[2 * d4.z],     w4.z * y2.x);
    atomicAdd(&g_araw[2 * d4.z + 1], w4.z * y2.y);
    atomicAdd(&g_araw[2 * d4.w],     w4.w * y3.x);
    atomicAdd(&g_araw[2 * d4.w + 1], w4.w * y3.y);
}

// ---------------- K7: pooling; out = gsum/cnt + b2 ----------------
__global__ void k_pool(const int* __restrict__ batch, const float* __restrict__ b2,
                       float* __restrict__ out, int nblocks) {
    __shared__ float ssum[2 * N_GRAPHS];
    __shared__ float scnt[N_GRAPHS];
    __shared__ bool  isLast;
    int t = threadIdx.x;
    if (t < 2 * N_GRAPHS) ssum[t] = 0.f;
    if (t < N_GRAPHS)     scnt[t] = 0.f;
    __syncthreads();

    int n = blockIdx.x * blockDim.x + t;
    if (n < N_NODES) {
        int g = batch[n];
        float di = g_dinv[n];
        float2 a = *reinterpret_cast<const float2*>(&g_araw[2 * n]);
        atomicAdd(&ssum[2 * g],     di * a.x);
        atomicAdd(&ssum[2 * g + 1], di * a.y);
        atomicAdd(&scnt[g], 1.0f);
    }
    __syncthreads();
    if (t < 2 * N_GRAPHS && ssum[t] != 0.f) atomicAdd(&g_gsum[t], ssum[t]);
    if (t < N_GRAPHS     && scnt[t] != 0.f) atomicAdd(&g_gcnt[t], scnt[t]);

    __threadfence();
    __syncthreads();
    if (t == 0) isLast = (atomicAdd(&g_done, 1u) == (unsigned)(nblocks - 1));
    __syncthreads();
    if (isLast && t < 2 * N_GRAPHS) {
        float cnt = fmaxf(g_gcnt[t >> 1], 1.0f);
        out[t] = g_gsum[t] / cnt + b2[t & 1];   // +b2 commutes with the mean
    }
}

// ---------------- launch ----------------
extern "C" void kernel_launch(void* const* d_in, const int* in_sizes, int n_in,
                              void* d_out, int out_size) {
    const float* x     = (const float*)d_in[0];
    const int*   ei    = (const int*)  d_in[1];
    const float* ew    = (const float*)d_in[2];
    const int*   batch = (const int*)  d_in[3];
    const float* W1    = (const float*)d_in[4];
    const float* gamma = (const float*)d_in[6];
    const float* beta  = (const float*)d_in[7];
    const float* W2    = (const float*)d_in[8];
    const float* b2    = (const float*)d_in[9];
    const int* src = ei;
    const int* dst = ei + N_EDGES;
    float* out = (float*)d_out;

    const int NT = 256;
    const int nodeBlocks = (N_NODES + NT - 1) / NT;            // 391
    const int edgeBlocks = (N_EDGES / 4 + NT - 1) / NT;        // 1563

    k_init <<<nodeBlocks, NT>>>();
    k_deg  <<<edgeBlocks, NT>>>(dst, ew);
    k_dinv <<<nodeBlocks, NT>>>(x);
    k_edge1<<<edgeBlocks, NT>>>(src, dst, ew);
    k_stats<<<nodeBlocks, NT>>>();
    k_node <<<nodeBlocks, NT>>>(W1, gamma, beta, W2);
    k_edge2<<<edgeBlocks, NT>>>(src, dst, ew);
    k_pool <<<nodeBlocks, NT>>>(batch, b2, out, nodeBlocks);
}

// round 3
// speedup vs baseline: 1.2356x; 1.0686x over previous
#include <cuda_runtime.h>

#define N_NODES  100000
#define N_EDGES  1600000
#define HIDDEN   64
#define N_GRAPHS 64

// Edge work partitioning: 8 edges per thread, two coalesced int4/float4 loads.
#define EQ  (N_EDGES / 4)          // 400000 int4 quads
#define ET  (EQ / 2)               // 200000 threads, each takes quad t and t+ET

// ---------------- scratch ----------------
__device__ float  g_deg  [N_NODES];
__device__ float  g_dinv [N_NODES];
__device__ float  g_q    [N_NODES];
__device__ float  g_praw [N_NODES];
__device__ float2 g_ysc  [N_NODES];   // dinv*y (gather source, layer 2)
__device__ float2 g_araw [N_NODES];   // layer-2 accumulator (8B aligned for red.v2)
__device__ float  g_stats[2];
__device__ float  g_gsum [2 * N_GRAPHS];
__device__ float  g_gcnt [N_GRAPHS];
__device__ unsigned g_done;

__device__ __forceinline__ void red_add_v2(float2* addr, float a, float b) {
    asm volatile("red.global.add.v2.f32 [%0], {%1, %2};"
                 :: "l"(addr), "f"(a), "f"(b) : "memory");
}

// ---------------- K0: zero accumulators ----------------
__global__ void k_init() {
    int i = blockIdx.x * blockDim.x + threadIdx.x;
    if (i < N_NODES) g_deg[i] = 0.0f;
    if (i < 2 * N_GRAPHS) g_gsum[i] = 0.0f;
    if (i < N_GRAPHS)     g_gcnt[i] = 0.0f;
    if (i < 2)            g_stats[i] = 0.0f;
    if (i == 0)           g_done = 0u;
}

// ---------------- K1: deg[dst] += ew  (8 edges/thread) ----------------
__global__ void k_deg(const int* __restrict__ dst, const float* __restrict__ ew) {
    int t = blockIdx.x * blockDim.x + threadIdx.x;
    if (t >= ET) return;
    int4   dA = reinterpret_cast<const int4*>(dst)[t];
    int4   dB = reinterpret_cast<const int4*>(dst)[t + ET];
    float4 wA = reinterpret_cast<const float4*>(ew)[t];
    float4 wB = reinterpret_cast<const float4*>(ew)[t + ET];
    atomicAdd(&g_deg[dA.x], wA.x);
    atomicAdd(&g_deg[dA.y], wA.y);
    atomicAdd(&g_deg[dA.z], wA.z);
    atomicAdd(&g_deg[dA.w], wA.w);
    atomicAdd(&g_deg[dB.x], wB.x);
    atomicAdd(&g_deg[dB.y], wB.y);
    atomicAdd(&g_deg[dB.z], wB.z);
    atomicAdd(&g_deg[dB.w], wB.w);
}

// ---------------- K2: dinv, q = dinv*x, praw init = q ----------------
__global__ void k_dinv(const float* __restrict__ x) {
    int n = blockIdx.x * blockDim.x + threadIdx.x;
    if (n >= N_NODES) return;
    float di = rsqrtf(g_deg[n] + 1.0f);
    float q  = x[n] * di;
    g_dinv[n] = di;
    g_q[n]    = q;
    g_praw[n] = q;
}

// ---------------- K3: praw[dst] += w * q[src]  (8 edges/thread) ----------------
__global__ void k_edge1(const int* __restrict__ src, const int* __restrict__ dst,
                        const float* __restrict__ ew) {
    int t = blockIdx.x * blockDim.x + threadIdx.x;
    if (t >= ET) return;
    int4   sA = reinterpret_cast<const int4*>(src)[t];
    int4   sB = reinterpret_cast<const int4*>(src)[t + ET];
    int4   dA = reinterpret_cast<const int4*>(dst)[t];
    int4   dB = reinterpret_cast<const int4*>(dst)[t + ET];
    float4 wA = reinterpret_cast<const float4*>(ew)[t];
    float4 wB = reinterpret_cast<const float4*>(ew)[t + ET];
    // issue all 8 gathers before any atomic (max MLP)
    float q0 = __ldg(&g_q[sA.x]), q1 = __ldg(&g_q[sA.y]);
    float q2 = __ldg(&g_q[sA.z]), q3 = __ldg(&g_q[sA.w]);
    float q4 = __ldg(&g_q[sB.x]), q5 = __ldg(&g_q[sB.y]);
    float q6 = __ldg(&g_q[sB.z]), q7 = __ldg(&g_q[sB.w]);
    atomicAdd(&g_praw[dA.x], wA.x * q0);
    atomicAdd(&g_praw[dA.y], wA.y * q1);
    atomicAdd(&g_praw[dA.z], wA.z * q2);
    atomicAdd(&g_praw[dA.w], wA.w * q3);
    atomicAdd(&g_praw[dB.x], wB.x * q4);
    atomicAdd(&g_praw[dB.y], wB.y * q5);
    atomicAdd(&g_praw[dB.z], wB.z * q6);
    atomicAdd(&g_praw[dB.w], wB.w * q7);
}

// ---------------- K4: stats over p = dinv*praw ----------------
__global__ void k_stats() {
    float s1 = 0.f, s2 = 0.f;
    for (int n = blockIdx.x * blockDim.x + threadIdx.x; n < N_NODES;
         n += gridDim.x * blockDim.x) {
        float v = g_dinv[n] * g_praw[n];
        s1 += v;
        s2 += v * v;
    }
    #pragma unroll
    for (int o = 16; o; o >>= 1) {
        s1 += __shfl_down_sync(0xFFFFFFFFu, s1, o);
        s2 += __shfl_down_sync(0xFFFFFFFFu, s2, o);
    }
    __shared__ float sh1[8], sh2[8];
    int wid = threadIdx.x >> 5, lid = threadIdx.x & 31;
    if (lid == 0) { sh1[wid] = s1; sh2[wid] = s2; }
    __syncthreads();
    if (wid == 0) {
        s1 = (lid < 8) ? sh1[lid] : 0.f;
        s2 = (lid < 8) ? sh2[lid] : 0.f;
        #pragma unroll
        for (int o = 4; o; o >>= 1) {
            s1 += __shfl_down_sync(0xFFFFFFFFu, s1, o);
            s2 += __shfl_down_sync(0xFFFFFFFFu, s2, o);
        }
        if (lid == 0) {
            atomicAdd(&g_stats[0], s1);
            atomicAdd(&g_stats[1], s2);
        }
    }
}

// ---------------- K5: BN+ReLU+W2; ysc = dinv*y; araw init = ysc ----------------
__global__ void k_node(const float* __restrict__ W1, const float* __restrict__ gamma,
                       const float* __restrict__ beta, const float* __restrict__ W2) {
    __shared__ float s_a[HIDDEN], s_b[HIDDEN], s_w0[HIDDEN], s_w1[HIDDEN];
    float mp  = g_stats[0] * (1.0f / N_NODES);
    float var = g_stats[1] * (1.0f / N_NODES) - mp * mp;
    int t = threadIdx.x;
    if (t < HIDDEN) {
        float w1c = W1[t];
        s_a[t]  = w1c * rsqrtf(var * w1c * w1c + 1e-5f) * gamma[t];
        s_b[t]  = beta[t];
        s_w0[t] = W2[2 * t];
        s_w1[t] = W2[2 * t + 1];
    }
    __syncthreads();
    int n = blockIdx.x * blockDim.x + threadIdx.x;
    if (n >= N_NODES) return;
    float di = g_dinv[n];
    float pm = di * g_praw[n] - mp;
    float y0 = 0.f, y1 = 0.f;
    #pragma unroll 16
    for (int c = 0; c < HIDDEN; c++) {
        float h = fmaf(pm, s_a[c], s_b[c]);
        h = fmaxf(h, 0.f);
        y0 = fmaf(h, s_w0[c], y0);
        y1 = fmaf(h, s_w1[c], y1);
    }
    float2 ysc = make_float2(y0 * di, y1 * di);
    g_ysc[n]  = ysc;
    g_araw[n] = ysc;
}

// ---------------- K6: araw[dst] += w * ysc[src]  (8 edges/thread, v2 RED) ----------------
__global__ void k_edge2(const int* __restrict__ src, const int* __restrict__ dst,
                        const float* __restrict__ ew) {
    int t = blockIdx.x * blockDim.x + threadIdx.x;
    if (t >= ET) return;
    int4   sA = reinterpret_cast<const int4*>(src)[t];
    int4   sB = reinterpret_cast<const int4*>(src)[t + ET];
    int4   dA = reinterpret_cast<const int4*>(dst)[t];
    int4   dB = reinterpret_cast<const int4*>(dst)[t + ET];
    float4 wA = reinterpret_cast<const float4*>(ew)[t];
    float4 wB = reinterpret_cast<const float4*>(ew)[t + ET];
    float2 y0 = g_ysc[sA.x];
    float2 y1 = g_ysc[sA.y];
    float2 y2 = g_ysc[sA.z];
    float2 y3 = g_ysc[sA.w];
    float2 y4 = g_ysc[sB.x];
    float2 y5 = g_ysc[sB.y];
    float2 y6 = g_ysc[sB.z];
    float2 y7 = g_ysc[sB.w];
    red_add_v2(&g_araw[dA.x], wA.x * y0.x, wA.x * y0.y);
    red_add_v2(&g_araw[dA.y], wA.y * y1.x, wA.y * y1.y);
    red_add_v2(&g_araw[dA.z], wA.z * y2.x, wA.z * y2.y);
    red_add_v2(&g_araw[dA.w], wA.w * y3.x, wA.w * y3.y);
    red_add_v2(&g_araw[dB.x], wB.x * y4.x, wB.x * y4.y);
    red_add_v2(&g_araw[dB.y], wB.y * y5.x, wB.y * y5.y);
    red_add_v2(&g_araw[dB.z], wB.z * y6.x, wB.z * y6.y);
    red_add_v2(&g_araw[dB.w], wB.w * y7.x, wB.w * y7.y);
}

// ---------------- K7: pooling; out = gsum/cnt + b2 ----------------
__global__ void k_pool(const int* __restrict__ batch, const float* __restrict__ b2,
                       float* __restrict__ out, int nblocks) {
    __shared__ float ssum[2 * N_GRAPHS];
    __shared__ float scnt[N_GRAPHS];
    __shared__ bool  isLast;
    int t = threadIdx.x;
    if (t < 2 * N_GRAPHS) ssum[t] = 0.f;
    if (t < N_GRAPHS)     scnt[t] = 0.f;
    __syncthreads();

    int n = blockIdx.x * blockDim.x + t;
    if (n < N_NODES) {
        int g = batch[n];
        float di = g_dinv[n];
        float2 a = g_araw[n];
        atomicAdd(&ssum[2 * g],     di * a.x);
        atomicAdd(&ssum[2 * g + 1], di * a.y);
        atomicAdd(&scnt[g], 1.0f);
    }
    __syncthreads();
    if (t < 2 * N_GRAPHS && ssum[t] != 0.f) atomicAdd(&g_gsum[t], ssum[t]);
    if (t < N_GRAPHS     && scnt[t] != 0.f) atomicAdd(&g_gcnt[t], scnt[t]);

    __threadfence();
    __syncthreads();
    if (t == 0) isLast = (atomicAdd(&g_done, 1u) == (unsigned)(nblocks - 1));
    __syncthreads();
    if (isLast && t < 2 * N_GRAPHS) {
        float cnt = fmaxf(g_gcnt[t >> 1], 1.0f);
        out[t] = g_gsum[t] / cnt + b2[t & 1];
    }
}

// ---------------- launch ----------------
extern "C" void kernel_launch(void* const* d_in, const int* in_sizes, int n_in,
                              void* d_out, int out_size) {
    const float* x     = (const float*)d_in[0];
    const int*   ei    = (const int*)  d_in[1];
    const float* ew    = (const float*)d_in[2];
    const int*   batch = (const int*)  d_in[3];
    const float* W1    = (const float*)d_in[4];
    const float* gamma = (const float*)d_in[6];
    const float* beta  = (const float*)d_in[7];
    const float* W2    = (const float*)d_in[8];
    const float* b2    = (const float*)d_in[9];
    const int* src = ei;
    const int* dst = ei + N_EDGES;
    float* out = (float*)d_out;

    const int NT = 256;
    const int nodeBlocks = (N_NODES + NT - 1) / NT;   // 391
    const int edgeBlocks = (ET + NT - 1) / NT;        // 782

    k_init <<<nodeBlocks, NT>>>();
    k_deg  <<<edgeBlocks, NT>>>(dst, ew);
    k_dinv <<<nodeBlocks, NT>>>(x);
    k_edge1<<<edgeBlocks, NT>>>(src, dst, ew);
    k_stats<<<nodeBlocks, NT>>>();
    k_node <<<nodeBlocks, NT>>>(W1, gamma, beta, W2);
    k_edge2<<<edgeBlocks, NT>>>(src, dst, ew);
    k_pool <<<nodeBlocks, NT>>>(batch, b2, out, nodeBlocks);
}